// round 10
// baseline (speedup 1.0000x reference)
#include <cuda_runtime.h>
#include <cuda_fp16.h>
#include <cstdint>

#define NUM_NEURONS 8192
#define INPUT_SIZE  8192
#define BATCH       2048

#define THREADS 1024
#define NPT     8                  // neurons per thread (2 groups of 4)
#define NGROUP  (NPT / 4)          // 2
#define GRID    148                // persistent: 1 block per SM
#define PAIRS   (BATCH / 2)        // 1024 row-pairs

// Per-neuron collapsed coefficients packed as half2: {A,B}, {C,D}
__device__ uint2 g_cffh[NUM_NEURONS];

__device__ __forceinline__ unsigned h2u(__half2 h) {
    return *reinterpret_cast<unsigned*>(&h);
}
__device__ __forceinline__ __half2 u2h(unsigned u) {
    return *reinterpret_cast<__half2*>(&u);
}

// ---------------------------------------------------------------------------
// Precompute: softmax(w[n,:16]) -> collapsed affine coefficients
// out = A + B*a1 + C*a2 + D*a1*a2, packed to half2 pairs.
// ---------------------------------------------------------------------------
__global__ void coeff_kernel(const float* __restrict__ w) {
    int n = blockIdx.x * blockDim.x + threadIdx.x;
    if (n >= NUM_NEURONS) return;

    const float4* wr = reinterpret_cast<const float4*>(w) + n * 4;
    float v[16];
    float4 t;
    t = wr[0]; v[0]=t.x;  v[1]=t.y;  v[2]=t.z;  v[3]=t.w;
    t = wr[1]; v[4]=t.x;  v[5]=t.y;  v[6]=t.z;  v[7]=t.w;
    t = wr[2]; v[8]=t.x;  v[9]=t.y;  v[10]=t.z; v[11]=t.w;
    t = wr[3]; v[12]=t.x; v[13]=t.y; v[14]=t.z; v[15]=t.w;

    float m = v[0];
#pragma unroll
    for (int i = 1; i < 16; i++) m = fmaxf(m, v[i]);
    float s = 0.0f;
#pragma unroll
    for (int i = 0; i < 16; i++) { v[i] = __expf(v[i] - m); s += v[i]; }
    float inv = 1.0f / s;
#pragma unroll
    for (int i = 0; i < 16; i++) v[i] *= inv;

    //  0:0  1:p  2:a1-p  3:a1  4:a2-p  5:a2  6:a1+a2-2p  7:a1+a2-p
    //  8:1-(a1+a2-p)  9:1-(a1+a2-2p)  10:1-a2  11:1-a2+p
    // 12:1-a1  13:1-a1+p  14:1-p  15:1
    float A = v[8]+v[9]+v[10]+v[11]+v[12]+v[13]+v[14]+v[15];
    float B = (v[2]+v[3]+v[6]+v[7]) - (v[8]+v[9]+v[12]+v[13]);
    float C = (v[4]+v[5]+v[6]+v[7]) - (v[8]+v[9]+v[10]+v[11]);
    float D = v[1]-v[2]-v[4]-2.0f*v[6]-v[7]+v[8]+2.0f*v[9]+v[11]+v[13]-v[14];

    g_cffh[n] = make_uint2(h2u(__floats2half2_rn(A, B)),
                           h2u(__floats2half2_rn(C, D)));
}

// Pack 2 rows x 8 columns of fp32 into half2 {row0,row1} and store to xh.
// dst[4t..4t+3] <- cols 4t..4t+3 (rows a/c), dst[4096+4t..] <- cols 4096+4t (b/d).
__device__ __forceinline__ void store_pack(__half2* dst, int tid,
                                           float4 a, float4 b, float4 c, float4 d) {
    uint4 s0 = make_uint4(h2u(__floats2half2_rn(a.x, c.x)),
                          h2u(__floats2half2_rn(a.y, c.y)),
                          h2u(__floats2half2_rn(a.z, c.z)),
                          h2u(__floats2half2_rn(a.w, c.w)));
    uint4 s1 = make_uint4(h2u(__floats2half2_rn(b.x, d.x)),
                          h2u(__floats2half2_rn(b.y, d.y)),
                          h2u(__floats2half2_rn(b.z, d.z)),
                          h2u(__floats2half2_rn(b.w, d.w)));
    reinterpret_cast<uint4*>(dst)[tid]        = s0;   // conflict-free STS.128
    reinterpret_cast<uint4*>(dst)[1024 + tid] = s1;
}

// ---------------------------------------------------------------------------
// Persistent main kernel. grid=148, 1 block/SM, 1024 threads, smem = 2x32KB
// half2 gather tables (double buffered). NO TMA: staging is LDG.128 ->
// registers -> half2 pack -> STS.128 (one crossbar write instead of
// TMA-write + LDS-reread + STS). Per iteration: issue LDGs for pair k+1,
// gather pair k (covers the DRAM latency), convert k+1 into the other xh
// buffer, ONE barrier. idx + half2-packed coefficients are register-resident.
// ---------------------------------------------------------------------------
__global__ __launch_bounds__(THREADS, 1) void logic_kernel(
    const float* __restrict__ x,
    const int*   __restrict__ idx,
    float* __restrict__ out)
{
    extern __shared__ __align__(128) __half2 xh[];   // [2][INPUT_SIZE]
    __half2* xh0 = xh;
    __half2* xh1 = xh + INPUT_SIZE;

    const int tid = threadIdx.x;
    const int bid = blockIdx.x;
    const float4* xp = reinterpret_cast<const float4*>(x);  // pair = 4096 float4

    // --- Preload idx (packed u16 pairs) + half2 coefficients into registers ---
    uint32_t pidx[NPT];
    uint2    cf[NPT];
    const int4*  idx4 = reinterpret_cast<const int4*>(idx);
    const uint4* cfp  = reinterpret_cast<const uint4*>(g_cffh);
#pragma unroll
    for (int g = 0; g < NGROUP; g++) {
        int nbase = g * (4 * THREADS) + tid * 4;   // 4 consecutive neurons
        int4 ia = __ldg(&idx4[nbase / 2]);
        int4 ib = __ldg(&idx4[nbase / 2 + 1]);
        pidx[g * 4 + 0] = (uint32_t)ia.x | ((uint32_t)ia.y << 16);
        pidx[g * 4 + 1] = (uint32_t)ia.z | ((uint32_t)ia.w << 16);
        pidx[g * 4 + 2] = (uint32_t)ib.x | ((uint32_t)ib.y << 16);
        pidx[g * 4 + 3] = (uint32_t)ib.z | ((uint32_t)ib.w << 16);
        uint4 ca = __ldg(&cfp[nbase / 2]);       // 2 neurons (uint2 each)
        uint4 cb = __ldg(&cfp[nbase / 2 + 1]);
        cf[g * 4 + 0] = make_uint2(ca.x, ca.y);
        cf[g * 4 + 1] = make_uint2(ca.z, ca.w);
        cf[g * 4 + 2] = make_uint2(cb.x, cb.y);
        cf[g * 4 + 3] = make_uint2(cb.z, cb.w);
    }

    const int npairs = (PAIRS - bid + GRID - 1) / GRID;   // 6 or 7

    // --- Prologue: stage pair 0 into xh0 ---
    {
        const size_t base = (size_t)bid * 4096;
        float4 a = __ldg(xp + base + tid);
        float4 b = __ldg(xp + base + 1024 + tid);
        float4 c = __ldg(xp + base + 2048 + tid);
        float4 d = __ldg(xp + base + 3072 + tid);
        store_pack(xh0, tid, a, b, c, d);
    }
    __syncthreads();

    for (int k = 0; k < npairs; k++) {
        const __half2* cur = (k & 1) ? xh1 : xh0;
        __half2*       nxt = (k & 1) ? xh0 : xh1;
        const bool havenext = (k + 1 < npairs);

        // Issue next pair's LDGs FIRST — gather below hides the DRAM latency.
        float4 La, Lb, Lc, Ld;
        if (havenext) {
            const size_t base = (size_t)(bid + (k + 1) * GRID) * 4096;
            La = __ldg(xp + base + tid);
            Lb = __ldg(xp + base + 1024 + tid);
            Lc = __ldg(xp + base + 2048 + tid);
            Ld = __ldg(xp + base + 3072 + tid);
        }

        // --- Gather + compute pair k ---
        const int p = bid + k * GRID;
        float4* o0 = reinterpret_cast<float4*>(out + (size_t)(2 * p)     * NUM_NEURONS);
        float4* o1 = reinterpret_cast<float4*>(out + (size_t)(2 * p + 1) * NUM_NEURONS);

#pragma unroll
        for (int g = 0; g < NGROUP; g++) {
            float4 r0, r1;
            float* q0 = reinterpret_cast<float*>(&r0);
            float* q1 = reinterpret_cast<float*>(&r1);
#pragma unroll
            for (int u = 0; u < 4; u++) {
                const uint32_t pk = pidx[g * 4 + u];
                const float2 a1 = __half22float2(cur[pk & 0xFFFFu]);  // {r0,r1}@i1
                const float2 a2 = __half22float2(cur[pk >> 16]);     // {r0,r1}@i2
                const float2 AB = __half22float2(u2h(cf[g * 4 + u].x));
                const float2 CD = __half22float2(u2h(cf[g * 4 + u].y));
                q0[u] = fmaf(a1.x, fmaf(a2.x, CD.y, AB.y), fmaf(a2.x, CD.x, AB.x));
                q1[u] = fmaf(a1.y, fmaf(a2.y, CD.y, AB.y), fmaf(a2.y, CD.x, AB.x));
            }
            const int o = g * THREADS + tid;   // coalesced float4 stores
            o0[o] = r0;
            o1[o] = r1;
        }

        // --- Convert pair k+1 into the other buffer (disjoint from cur) ---
        if (havenext) store_pack(nxt, tid, La, Lb, Lc, Ld);

        __syncthreads();   // gather-k reads done + convert-(k+1) visible
    }
}

extern "C" void kernel_launch(void* const* d_in, const int* in_sizes, int n_in,
                              void* d_out, int out_size) {
    const float* x    = (const float*)d_in[0];   // [2048, 8192] f32
    const float* w    = (const float*)d_in[1];   // [8192, 16]   f32
    const int*   conn = (const int*)d_in[2];     // [8192, 2]    i32
    float* out = (float*)d_out;                  // [2048, 8192] f32

    const int smem = 2 * INPUT_SIZE * sizeof(__half2);   // 64 KB
    cudaFuncSetAttribute(logic_kernel,
                         cudaFuncAttributeMaxDynamicSharedMemorySize, smem);

    coeff_kernel<<<NUM_NEURONS / 256, 256>>>(w);
    logic_kernel<<<GRID, THREADS, smem>>>(x, conn, out);
}